// round 16
// baseline (speedup 1.0000x reference)
#include <cuda_runtime.h>

// Problem constants
#define T_  4
#define B_  16
#define C_  512
#define N_  1024
#define CR_ 64
#define TB_ (T_ * B_)          // 64
#define BN_EPS 1e-5f
#define NBLK_ (B_ * C_)        // 8192 blocks

// Scratch (allocation-free rule: __device__ globals)
__device__ float g_gap[TB_ * C_];   // [64, 512]
__device__ float g_h1[TB_ * CR_];   // [64, 64]

// Finisher-ticket counter + MLP-internal barrier.
// All are reset by the barrier-2 releaser each run -> graph-replay safe.
__device__ unsigned g_ticket = 0;
__device__ unsigned g_bar2_count = 0;
__device__ volatile unsigned g_bar2_gen = 0;

// ---------------------------------------------------------------------------
// ONE kernel, 8192 blocks x 256 threads (R8-proven LIF shape, 77% DRAM).
// After publishing its GAP tile each block takes a ticket; the last 64
// finishers become the MLP blocks: stage weights (overlapped with the wait
// for stragglers), spin until all tickets taken (g complete + L2-hot), then
// run FC1+BN1 -> 64-block barrier -> FC2+BN2. No second launch, no ramp.
// launch_bounds(256,7): regs <= 36 so LIF occupancy stays ~7 blocks/SM.
// ---------------------------------------------------------------------------
__global__ void __launch_bounds__(256, 7)
snn_kernel(const float* __restrict__ x,
           const float* __restrict__ w1,
           const float* __restrict__ b1,
           const float* __restrict__ gamma1,
           const float* __restrict__ beta1,
           const float* __restrict__ w2,
           const float* __restrict__ b2,
           const float* __restrict__ gamma2,
           const float* __restrict__ beta2,
           float* __restrict__ g,
           float* __restrict__ h1,
           float* __restrict__ out) {
    const int bc  = blockIdx.x;          // 0..8191
    const int b   = bc >> 9;             // /512
    const int c   = bc & (C_ - 1);
    const int tid = threadIdx.x;
    const int lane = tid & 31;
    const int wid  = tid >> 5;

    // ======================= LIF + GAP (R8 shape) ===========================
    {
        const size_t strideT = (size_t)B_ * C_ * N_;
        const size_t base = ((size_t)b * C_ + c) * N_ + (size_t)tid * 4;

        float4 xt[T_];
#pragma unroll
        for (int t = 0; t < T_; t++)
            xt[t] = __ldcs(reinterpret_cast<const float4*>(x + base + (size_t)t * strideT));

        float sums[T_] = {0.f, 0.f, 0.f, 0.f};
#pragma unroll
        for (int slot = 0; slot < 4; slot++) {
            float v = 0.f;
#pragma unroll
            for (int t = 0; t < T_; t++) {
                float xv = (slot == 0) ? xt[t].x : (slot == 1) ? xt[t].y
                         : (slot == 2) ? xt[t].z : xt[t].w;
                v = 0.5f * (v + xv);                 // v += (x - v)/TAU, TAU=2
                float s = (v >= 1.0f) ? 1.0f : 0.0f; // spike(v - V_TH)
                sums[t] += s;
                v *= (1.0f - s);                     // hard reset (detached)
            }
        }

        __shared__ float red[8][T_];
#pragma unroll
        for (int t = 0; t < T_; t++) {
#pragma unroll
            for (int off = 16; off > 0; off >>= 1)
                sums[t] += __shfl_xor_sync(0xFFFFFFFFu, sums[t], off);
        }
        if (lane == 0) {
#pragma unroll
            for (int t = 0; t < T_; t++) red[wid][t] = sums[t];
        }
        __syncthreads();
        if (tid < T_) {
            float tot = 0.f;
#pragma unroll
            for (int w = 0; w < 8; w++) tot += red[w][tid];
            g[((tid * B_ + b) * C_) + c] = tot * (1.0f / (float)N_);
        }
    }
    __syncthreads();

    // ======================= Ticket: am I a finisher? =======================
    __shared__ unsigned s_ticket;
    if (tid == 0) {
        __threadfence();                     // publish this block's g values
        s_ticket = atomicAdd(&g_ticket, 1u);
    }
    __syncthreads();
    const unsigned tkt = s_ticket;
    if (tkt < NBLK_ - CR_) return;           // 8128 blocks exit; 64 remain
    const int j = (int)(tkt - (NBLK_ - CR_)); // MLP role / FC1 column 0..63

    // ======================= MLP prologue (overlaps the wait) ===============
    __shared__ float4 w1s[C_ / 4];           // 2 KB: w1 row j
    __shared__ float4 w2s[8 * 16];           // 2 KB: w2 rows j*8..j*8+7
    __shared__ float  hrow[TB_];
    __shared__ float  ss[4][2], sq[4][2];
    __shared__ float  ss1[4][2], sq1[4][2];

    const int grp = tid >> 6;                // 0..3 (phase-2 column group)
    const int gt  = tid & 63;                // phase-2 batch row
    const int gw  = (tid >> 5) & 1;
    const int jj0 = j * 8 + grp;
    const int jj1 = j * 8 + 4 + grp;

    const float b1j  = b1[j];
    const float g1j  = gamma1[j];
    const float be1j = beta1[j];
    const float b20  = b2[jj0],     b21  = b2[jj1];
    const float gm20 = gamma2[jj0], gm21 = gamma2[jj1];
    const float bt20 = beta2[jj0],  bt21 = beta2[jj1];

    if (tid < C_ / 4) {
        w1s[tid] = reinterpret_cast<const float4*>(w1 + (size_t)j * C_)[tid];
    } else {
        const int m = tid - C_ / 4;          // 0..127 -> 8 rows x 16 float4
        w2s[m] = reinterpret_cast<const float4*>(w2)[(size_t)j * 128 + m];
    }

    // Wait for ALL tickets (=> every g tile written + fenced)
    if (tid == 0) {
        while (*(volatile unsigned*)&g_ticket < NBLK_) __nanosleep(40);
    }
    __syncthreads();
    __threadfence();                         // acquire g

    // ======================= Phase 1: FC1 + BN1 =============================
    {
        const int w = tid >> 5, l = tid & 31;
#pragma unroll
        for (int r = 0; r < 8; r++) {
            const int i = w * 8 + r;                       // batch row 0..63
            const float4* gr = reinterpret_cast<const float4*>(g + (size_t)i * C_);
            float acc = 0.f;
#pragma unroll
            for (int s = 0; s < 4; s++) {                  // 32-lane coalesced
                float4 a = gr[l + s * 32], wv = w1s[l + s * 32];
                acc += a.x * wv.x + a.y * wv.y + a.z * wv.z + a.w * wv.w;
            }
#pragma unroll
            for (int off = 16; off > 0; off >>= 1)
                acc += __shfl_xor_sync(0xFFFFFFFFu, acc, off);
            if (l == 0) hrow[i] = acc + b1j;
        }
    }
    __syncthreads();

    if (tid < TB_) {
        float h = hrow[tid];
        float s = h, q = h * h;
#pragma unroll
        for (int off = 16; off > 0; off >>= 1) {
            s += __shfl_xor_sync(0xFFFFFFFFu, s, off);
            q += __shfl_xor_sync(0xFFFFFFFFu, q, off);
        }
        if ((tid & 31) == 0) { ss[0][tid >> 5] = s; sq[0][tid >> 5] = q; }
    }
    __syncthreads();
    if (tid < TB_) {
        float mu  = (ss[0][0] + ss[0][1]) * (1.0f / (float)TB_);
        float ex2 = (sq[0][0] + sq[0][1]) * (1.0f / (float)TB_);
        float var = ex2 - mu * mu;
        h1[tid * CR_ + j] = (hrow[tid] - mu) * rsqrtf(var + BN_EPS) * g1j + be1j;
    }
    __syncthreads();

    // ======================= Barrier among the 64 MLP blocks ================
    if (tid == 0) {
        __threadfence();                     // publish h1
        unsigned gen = g_bar2_gen;
        unsigned old = atomicAdd(&g_bar2_count, 1);
        if (old == CR_ - 1) {
            g_bar2_count = 0;
            g_ticket = 0;                    // reset for next graph replay
            __threadfence();
            g_bar2_gen = gen + 1;            // release
        } else {
            while (g_bar2_gen == gen) __nanosleep(40);
        }
    }
    __syncthreads();
    __threadfence();                         // acquire h1

    // ======================= Phase 2: FC2 + BN2 =============================
    {
        const float4* hr = reinterpret_cast<const float4*>(h1 + (size_t)gt * CR_);
        const int rr0 = grp, rr1 = 4 + grp;
        float a00=0.f, a01=0.f, a02=0.f, a03=0.f;
        float a10=0.f, a11=0.f, a12=0.f, a13=0.f;
#pragma unroll
        for (int k = 0; k < CR_ / 16; k++) {
            float4 x0 = hr[k*4+0], x1 = hr[k*4+1], x2 = hr[k*4+2], x3 = hr[k*4+3];
            float4 u0 = w2s[rr0*16 + k*4+0], u1 = w2s[rr0*16 + k*4+1];
            float4 u2 = w2s[rr0*16 + k*4+2], u3 = w2s[rr0*16 + k*4+3];
            float4 v0 = w2s[rr1*16 + k*4+0], v1 = w2s[rr1*16 + k*4+1];
            float4 v2 = w2s[rr1*16 + k*4+2], v3 = w2s[rr1*16 + k*4+3];
            a00 += x0.x*u0.x + x0.y*u0.y + x0.z*u0.z + x0.w*u0.w;
            a01 += x1.x*u1.x + x1.y*u1.y + x1.z*u1.z + x1.w*u1.w;
            a02 += x2.x*u2.x + x2.y*u2.y + x2.z*u2.z + x2.w*u2.w;
            a03 += x3.x*u3.x + x3.y*u3.y + x3.z*u3.z + x3.w*u3.w;
            a10 += x0.x*v0.x + x0.y*v0.y + x0.z*v0.z + x0.w*v0.w;
            a11 += x1.x*v1.x + x1.y*v1.y + x1.z*v1.z + x1.w*v1.w;
            a12 += x2.x*v2.x + x2.y*v2.y + x2.z*v2.z + x2.w*v2.w;
            a13 += x3.x*v3.x + x3.y*v3.y + x3.z*v3.z + x3.w*v3.w;
        }
        float h0  = (a00 + a01) + (a02 + a03) + b20;
        float h1v = (a10 + a11) + (a12 + a13) + b21;

        float s0 = h0, q0 = h0 * h0, s1 = h1v, q1 = h1v * h1v;
#pragma unroll
        for (int off = 16; off > 0; off >>= 1) {
            s0 += __shfl_xor_sync(0xFFFFFFFFu, s0, off);
            q0 += __shfl_xor_sync(0xFFFFFFFFu, q0, off);
            s1 += __shfl_xor_sync(0xFFFFFFFFu, s1, off);
            q1 += __shfl_xor_sync(0xFFFFFFFFu, q1, off);
        }
        if ((gt & 31) == 0) {
            ss[grp][gw] = s0;  sq[grp][gw] = q0;
            ss1[grp][gw] = s1; sq1[grp][gw] = q1;
        }
        __syncthreads();
        {
            float mu  = (ss[grp][0] + ss[grp][1]) * (1.0f / (float)TB_);
            float ex2 = (sq[grp][0] + sq[grp][1]) * (1.0f / (float)TB_);
            float var = ex2 - mu * mu;
            out[gt * C_ + jj0] = (h0 - mu) * rsqrtf(var + BN_EPS) * gm20 + bt20;
        }
        {
            float mu  = (ss1[grp][0] + ss1[grp][1]) * (1.0f / (float)TB_);
            float ex2 = (sq1[grp][0] + sq1[grp][1]) * (1.0f / (float)TB_);
            float var = ex2 - mu * mu;
            out[gt * C_ + jj1] = (h1v - mu) * rsqrtf(var + BN_EPS) * gm21 + bt21;
        }
    }
}

// ---------------------------------------------------------------------------
extern "C" void kernel_launch(void* const* d_in, const int* in_sizes, int n_in,
                              void* d_out, int out_size) {
    const float* x      = (const float*)d_in[0];
    const float* w1     = (const float*)d_in[1];
    const float* b1     = (const float*)d_in[2];
    const float* gamma1 = (const float*)d_in[3];
    const float* beta1  = (const float*)d_in[4];
    const float* w2     = (const float*)d_in[5];
    const float* b2     = (const float*)d_in[6];
    const float* gamma2 = (const float*)d_in[7];
    const float* beta2  = (const float*)d_in[8];
    float* out = (float*)d_out;

    float* g;  cudaGetSymbolAddress((void**)&g,  g_gap);
    float* h1; cudaGetSymbolAddress((void**)&h1, g_h1);

    snn_kernel<<<NBLK_, 256>>>(x, w1, b1, gamma1, beta1,
                               w2, b2, gamma2, beta2, g, h1, out);
}

// round 17
// speedup vs baseline: 1.4068x; 1.4068x over previous
#include <cuda_runtime.h>

// Problem constants
#define T_  4
#define B_  16
#define C_  512
#define N_  1024
#define CR_ 64
#define TB_ (T_ * B_)          // 64
#define BN_EPS 1e-5f

// Scratch (allocation-free rule: __device__ globals)
__device__ float g_gap[TB_ * C_];    // [64, 512]  GAP output (row-major [i][c])
__device__ float g_hpre[CR_ * TB_];  // [64, 64]   FC1 pre-BN, TRANSPOSED [j][i]

// Grid barrier (generation counter survives graph replays)
__device__ unsigned g_bar_count = 0;
__device__ volatile unsigned g_bar_gen = 0;

// ---------------------------------------------------------------------------
// K1: LIF over T=4 + GAP over N. One block per (b, c): 8192 blocks, 256 thr.
// (R8-proven shape: 77% DRAM, occ 89%.) No atomics, no prefetch.
// ---------------------------------------------------------------------------
__global__ void __launch_bounds__(256) lif_gap_kernel(const float* __restrict__ x,
                                                      float* __restrict__ g) {
    const int bc  = blockIdx.x;          // 0..8191
    const int b   = bc >> 9;             // /512
    const int c   = bc & (C_ - 1);
    const int tid = threadIdx.x;

    const size_t strideT = (size_t)B_ * C_ * N_;
    const size_t base = ((size_t)b * C_ + c) * N_ + (size_t)tid * 4;

    // Front-batched: 4 independent float4 streaming loads
    float4 xt[T_];
#pragma unroll
    for (int t = 0; t < T_; t++)
        xt[t] = __ldcs(reinterpret_cast<const float4*>(x + base + (size_t)t * strideT));

    float sums[T_] = {0.f, 0.f, 0.f, 0.f};
#pragma unroll
    for (int slot = 0; slot < 4; slot++) {
        float v = 0.f;
#pragma unroll
        for (int t = 0; t < T_; t++) {
            float xv = (slot == 0) ? xt[t].x : (slot == 1) ? xt[t].y
                     : (slot == 2) ? xt[t].z : xt[t].w;
            v = 0.5f * (v + xv);                 // v += (x - v)/TAU, TAU=2
            float s = (v >= 1.0f) ? 1.0f : 0.0f; // spike(v - V_TH)
            sums[t] += s;
            v *= (1.0f - s);                     // hard reset (detached)
        }
    }

    __shared__ float red[8][T_];
    const int lane = tid & 31;
    const int wid  = tid >> 5;
#pragma unroll
    for (int t = 0; t < T_; t++) {
#pragma unroll
        for (int off = 16; off > 0; off >>= 1)
            sums[t] += __shfl_xor_sync(0xFFFFFFFFu, sums[t], off);
    }
    if (lane == 0) {
#pragma unroll
        for (int t = 0; t < T_; t++) red[wid][t] = sums[t];
    }
    __syncthreads();

    if (tid < T_) {
        float tot = 0.f;
#pragma unroll
        for (int w = 0; w < 8; w++) tot += red[w][tid];
        g[((tid * B_ + b) * C_) + c] = tot * (1.0f / (float)N_);
    }
}

// ---------------------------------------------------------------------------
// K2: MLP, 512 blocks x 128 threads (all co-resident: ~3.5 blocks/SM).
// Phase 1 (block = (j, rowgroup)): 8 entries of h_pre[j][i] (transposed).
// Grid barrier (512 arrivals).
// Phase 2 (block = FC2 column jj, 0..511): redundant BN1 stats from L2-hot
// h_pre (16 KB), fold BN1 into wmod/Cshift, 64-dot per row, in-block BN2.
// ---------------------------------------------------------------------------
__global__ void __launch_bounds__(128) mlp_kernel(const float* __restrict__ g,
                                                  const float* __restrict__ w1,
                                                  const float* __restrict__ b1,
                                                  const float* __restrict__ gamma1,
                                                  const float* __restrict__ beta1,
                                                  const float* __restrict__ w2,
                                                  const float* __restrict__ b2,
                                                  const float* __restrict__ gamma2,
                                                  const float* __restrict__ beta2,
                                                  float* __restrict__ hpre,
                                                  float* __restrict__ out) {
    const int tid = threadIdx.x;
    const int w   = tid >> 5, l = tid & 31;

    // ================= Phase 1: h_pre[j][i] = g[i,:] . w1[j,:] + b1[j] ======
    {
        const int j  = blockIdx.x & 63;        // FC1 output column
        const int rg = blockIdx.x >> 6;        // row group 0..7
        const int i0 = rg * 8 + w * 2;         // this warp's 2 rows

        const float  b1j = b1[j];
        const float4* w1r = reinterpret_cast<const float4*>(w1 + (size_t)j * C_);
        const float4* g40 = reinterpret_cast<const float4*>(g + (size_t)i0 * C_);
        const float4* g41 = reinterpret_cast<const float4*>(g + (size_t)(i0 + 1) * C_);

        // 12 independent loads front-batched (4 w1 + 2x4 g)
        float4 wv[4], a0[4], a1[4];
#pragma unroll
        for (int s = 0; s < 4; s++) {
            wv[s] = w1r[l + s * 32];
            a0[s] = g40[l + s * 32];
            a1[s] = g41[l + s * 32];
        }
        float acc0 = 0.f, acc1 = 0.f;
#pragma unroll
        for (int s = 0; s < 4; s++) {
            acc0 += a0[s].x * wv[s].x + a0[s].y * wv[s].y
                  + a0[s].z * wv[s].z + a0[s].w * wv[s].w;
            acc1 += a1[s].x * wv[s].x + a1[s].y * wv[s].y
                  + a1[s].z * wv[s].z + a1[s].w * wv[s].w;
        }
#pragma unroll
        for (int off = 16; off > 0; off >>= 1) {
            acc0 += __shfl_xor_sync(0xFFFFFFFFu, acc0, off);
            acc1 += __shfl_xor_sync(0xFFFFFFFFu, acc1, off);
        }
        if (l == 0) {
            hpre[j * TB_ + i0]     = acc0 + b1j;   // transposed [j][i]
            hpre[j * TB_ + i0 + 1] = acc1 + b1j;
        }
    }

    // ================= Grid barrier (512 co-resident blocks) ================
    __threadfence();                       // publish h_pre (all threads)
    __syncthreads();
    if (tid == 0) {
        unsigned gen = g_bar_gen;
        unsigned old = atomicAdd(&g_bar_count, 1);
        if (old == 511u) {
            g_bar_count = 0;
            __threadfence();
            g_bar_gen = gen + 1;           // release
        } else {
            while (g_bar_gen == gen) __nanosleep(40);
        }
    }
    __syncthreads();
    __threadfence();                       // acquire h_pre

    // ================= Phase 2: out[:, jj] ==================================
    const int jj = blockIdx.x;             // 0..511

    __shared__ float w2row[CR_];           // w2[jj, :]
    __shared__ float wmod[CR_];            // scale_j * w2row[j]
    __shared__ float shmul[CR_];           // shift_j (BN1 fold)
    __shared__ float cs2[2], ss2[2], sq2[2];

    if (tid < 16)
        reinterpret_cast<float4*>(w2row)[tid] =
            reinterpret_cast<const float4*>(w2 + (size_t)jj * CR_)[tid];

    // BN1 stats: thread t owns column t of h_pre (contiguous 64 floats).
    if (tid < CR_) {
        const float4* col = reinterpret_cast<const float4*>(hpre + (size_t)tid * TB_);
        float4 v[16];
#pragma unroll
        for (int k = 0; k < 16; k++) v[k] = col[k];   // 16 independent loads
        float s = 0.f, q = 0.f;
#pragma unroll
        for (int k = 0; k < 16; k++) {
            s += v[k].x + v[k].y + v[k].z + v[k].w;
            q += v[k].x * v[k].x + v[k].y * v[k].y
               + v[k].z * v[k].z + v[k].w * v[k].w;
        }
        const float mu  = s * (1.0f / (float)TB_);
        const float var = q * (1.0f / (float)TB_) - mu * mu;
        const float sc  = rsqrtf(var + BN_EPS) * gamma1[tid];
        wmod[tid]  = sc;                       // temp: scale_j (mult by w2row after sync)
        shmul[tid] = beta1[tid] - mu * sc;     // shift_j
    }
    __syncthreads();

    // Fold: wmod[j] = scale_j * w2row[j]; Cshift = sum_j shift_j * w2row[j]
    float csp = 0.f;
    if (tid < CR_) {
        const float wr = w2row[tid];
        wmod[tid] = wmod[tid] * wr;
        csp = shmul[tid] * wr;
#pragma unroll
        for (int off = 16; off > 0; off >>= 1)
            csp += __shfl_xor_sync(0xFFFFFFFFu, csp, off);
        if ((tid & 31) == 0) cs2[tid >> 5] = csp;
    }
    __syncthreads();

    // Dot per row i: h0(i) = sum_j hpre[j][i]*wmod[j] + Cshift + b2[jj]
    float outv = 0.f;
    float mu2, rs2;
    if (tid < TB_) {
        const int i = tid;
        float a0 = 0.f, a1 = 0.f, a2 = 0.f, a3 = 0.f;
#pragma unroll
        for (int jb = 0; jb < CR_; jb += 4) {      // coalesced across threads
            a0 += hpre[(jb + 0) * TB_ + i] * wmod[jb + 0];
            a1 += hpre[(jb + 1) * TB_ + i] * wmod[jb + 1];
            a2 += hpre[(jb + 2) * TB_ + i] * wmod[jb + 2];
            a3 += hpre[(jb + 3) * TB_ + i] * wmod[jb + 3];
        }
        const float h0 = (a0 + a1) + (a2 + a3) + (cs2[0] + cs2[1]) + b2[jj];

        // BN2 stats over the 64 rows (2 warps + smem combine)
        float s = h0, q = h0 * h0;
#pragma unroll
        for (int off = 16; off > 0; off >>= 1) {
            s += __shfl_xor_sync(0xFFFFFFFFu, s, off);
            q += __shfl_xor_sync(0xFFFFFFFFu, q, off);
        }
        if ((tid & 31) == 0) { ss2[tid >> 5] = s; sq2[tid >> 5] = q; }
        outv = h0;
    }
    __syncthreads();
    if (tid < TB_) {
        mu2 = (ss2[0] + ss2[1]) * (1.0f / (float)TB_);
        const float ex2 = (sq2[0] + sq2[1]) * (1.0f / (float)TB_);
        rs2 = rsqrtf(ex2 - mu2 * mu2 + BN_EPS);
        out[tid * C_ + jj] = (outv - mu2) * rs2 * gamma2[jj] + beta2[jj];
    }
}

// ---------------------------------------------------------------------------
extern "C" void kernel_launch(void* const* d_in, const int* in_sizes, int n_in,
                              void* d_out, int out_size) {
    const float* x      = (const float*)d_in[0];
    const float* w1     = (const float*)d_in[1];
    const float* b1     = (const float*)d_in[2];
    const float* gamma1 = (const float*)d_in[3];
    const float* beta1  = (const float*)d_in[4];
    const float* w2     = (const float*)d_in[5];
    const float* b2     = (const float*)d_in[6];
    const float* gamma2 = (const float*)d_in[7];
    const float* beta2  = (const float*)d_in[8];
    float* out = (float*)d_out;

    float* g;    cudaGetSymbolAddress((void**)&g,    g_gap);
    float* hpre; cudaGetSymbolAddress((void**)&hpre, g_hpre);

    lif_gap_kernel<<<B_ * C_, 256>>>(x, g);
    mlp_kernel<<<C_, 128>>>(g, w1, b1, gamma1, beta1,
                            w2, b2, gamma2, beta2, hpre, out);
}